// round 16
// baseline (speedup 1.0000x reference)
#include <cuda_runtime.h>
#include <math.h>

// Problem constants (fixed: features [512,384] f32, labels [512] i32)
#define NQ 512
#define DIM 384
#define KSPLIT 6
#define KCH 64               // K per gram job
#define TS 64                // gram tile size (M and N)
#define KC 16                // gram k-chunk
#define NJOBS (KSPLIT * (NQ / TS) * (NQ / TS))   // 6*8*8 = 384
#define SCALE 50.0f          // 1/(2*t2): sigmoid(z) = 0.5 + 0.5*tanh(z/2)
#define KSEL 6.0f            // K = 5 + 1

// Scratch (no allocations allowed anywhere)
__device__ float g_part[KSPLIT * NQ * NQ];  // partial Gram matrices (6 MB, L2-resident)
__device__ float g_sqp[KSPLIT * NQ];        // partial diagonal (squared norms)
__device__ float g_prec[NQ];                // per-query precision sums
__device__ unsigned int g_bar = 0;          // grid barrier arrivals
__device__ unsigned int g_count = 0;        // per-query completion tickets

__device__ __forceinline__ float fast_tanh(float x) {
    float r;
    asm("tanh.approx.f32 %0, %1;" : "=f"(r) : "f"(x));
    return r;
}

// packed fp32 pair FMA: acc.xy += a.xy * b.xy  (SASS FFMA2; sm_100a+)
#define FFMA2(acc, a, b) \
    asm("fma.rn.f32x2 %0, %1, %2, %0;" : "+l"(acc) : "l"(a), "l"(b))

// ---------------------------------------------------------------------------
// ONE persistent kernel (grid = 3 * #SM, launch_bounds guarantees residency).
//  Phase 1: gram jobs with FFMA2 microkernel. A stored DUPLICATED in smem
//           ((a,a) pairs, warp-broadcast loads), B natural pairs.
//           Per kk: 3x LDS.128 + 8x FFMA2 for a 4x4 microtile.
//  Grid barrier, then Phase 2: direct tanh-rank of label-matched items.
// ---------------------------------------------------------------------------
__global__ __launch_bounds__(256, 3) void fused_kernel(const float* __restrict__ F,
                                                       const int* __restrict__ labels,
                                                       float* __restrict__ out) {
    __shared__ float Ad[KC][2 * TS + 4];   // gram A, duplicated pairs [k][2m]
    __shared__ float Bs[KC][TS + 4];       // gram B [k][n]
    __shared__ float sq[NQ];               // summed squared norms
    __shared__ float va[NQ];               // val by gallery index
    __shared__ int   sl[NQ];               // labels staged
    __shared__ int   mlist[NQ];            // matched gallery indices
    __shared__ int   wcount[16];           // ballot counts (2 halves x 8 warps)
    __shared__ float ws[8];
    __shared__ int isLast;

    const int t   = threadIdx.x;
    const int wid = t >> 5;
    const int lid = t & 31;
    const unsigned GRID = gridDim.x;

    // ================= Phase 1: gram jobs (grid-stride) =================
    for (int job = blockIdx.x; job < NJOBS; job += GRID) {
        const int jz  = job >> 6;            // K split 0..5
        const int rem = job & 63;
        const int bm  = (rem >> 3) * TS;
        const int bn  = (rem & 7) * TS;
        const int kb  = jz * KCH;
        const int tr = t >> 4, tc = t & 15;  // 4-row group, 4-col group
        const int lr = t >> 2, lc = (t & 3) * 4;

        // acc[i][jp] = packed pair (col 4*tc+2*jp, 4*tc+2*jp+1) for row 4*tr+i
        unsigned long long accp[4][2] = {};

        for (int k0 = kb; k0 < kb + KCH; k0 += KC) {
            float4 av = *reinterpret_cast<const float4*>(&F[(bm + lr) * DIM + k0 + lc]);
            Ad[lc + 0][2 * lr] = av.x; Ad[lc + 0][2 * lr + 1] = av.x;
            Ad[lc + 1][2 * lr] = av.y; Ad[lc + 1][2 * lr + 1] = av.y;
            Ad[lc + 2][2 * lr] = av.z; Ad[lc + 2][2 * lr + 1] = av.z;
            Ad[lc + 3][2 * lr] = av.w; Ad[lc + 3][2 * lr + 1] = av.w;
            float4 bv = *reinterpret_cast<const float4*>(&F[(bn + lr) * DIM + k0 + lc]);
            Bs[lc + 0][lr] = bv.x; Bs[lc + 1][lr] = bv.y;
            Bs[lc + 2][lr] = bv.z; Bs[lc + 3][lr] = bv.w;
            __syncthreads();
            #pragma unroll
            for (int kk = 0; kk < KC; kk++) {
                // A dup pairs (a_i,a_i), i=0..3: warp-broadcast LDS.128 x2
                ulonglong2 a01 = *reinterpret_cast<const ulonglong2*>(&Ad[kk][8 * tr]);
                ulonglong2 a23 = *reinterpret_cast<const ulonglong2*>(&Ad[kk][8 * tr + 4]);
                // B natural pairs (b0,b1),(b2,b3): one LDS.128
                ulonglong2 b   = *reinterpret_cast<const ulonglong2*>(&Bs[kk][4 * tc]);
                FFMA2(accp[0][0], a01.x, b.x); FFMA2(accp[0][1], a01.x, b.y);
                FFMA2(accp[1][0], a01.y, b.x); FFMA2(accp[1][1], a01.y, b.y);
                FFMA2(accp[2][0], a23.x, b.x); FFMA2(accp[2][1], a23.x, b.y);
                FFMA2(accp[3][0], a23.y, b.x); FFMA2(accp[3][1], a23.y, b.y);
            }
            __syncthreads();
        }
        float* dst = g_part + jz * (NQ * NQ);
        #pragma unroll
        for (int i = 0; i < 4; i++) {
            #pragma unroll
            for (int jp = 0; jp < 2; jp++) {
                const float2 v = *reinterpret_cast<const float2*>(&accp[i][jp]);
                const int r = bm + 4 * tr + i;
                const int c = bn + 4 * tc + 2 * jp;
                dst[r * NQ + c]     = v.x;
                dst[r * NQ + c + 1] = v.y;
                if (r == c)     g_sqp[jz * NQ + r] = v.x;
                if (r == c + 1) g_sqp[jz * NQ + r] = v.y;
            }
        }
    }

    // ================= Grid barrier (all blocks resident) =================
    __syncthreads();
    if (t == 0) {
        __threadfence();
        atomicAdd(&g_bar, 1u);
        while (atomicAdd(&g_bar, 0u) < GRID) __nanosleep(64);
        __threadfence();
    }
    __syncthreads();

    // ================= Phase 2: queries (grid-stride) =================
    for (int q = blockIdx.x; q < NQ; q += (int)GRID) {
        float gq0 = 0.0f, gq1 = 0.0f;
        {
            float s0 = 0.0f, s1 = 0.0f;
            #pragma unroll
            for (int z = 0; z < KSPLIT; z++) {
                s0 += g_sqp[z * NQ + t];
                s1 += g_sqp[z * NQ + t + 256];
            }
            sq[t] = s0; sq[t + 256] = s1;
        }
        sl[t] = labels[t]; sl[t + 256] = labels[t + 256];
        {
            const int od = q * NQ;
            #pragma unroll
            for (int z = 0; z < KSPLIT; z++) {
                gq0 += g_part[z * NQ * NQ + od + t];
                gq1 += g_part[z * NQ * NQ + od + t + 256];
            }
        }
        __syncthreads();
        const float sqq = sq[q];
        va[t]       = SCALE * sqrtf(fmaxf(sqq + sq[t]       - 2.0f * gq0, 0.0f));
        va[t + 256] = SCALE * sqrtf(fmaxf(sqq + sq[t + 256] - 2.0f * gq1, 0.0f));
        const int Lq = sl[q];

        // deterministic matched list (half 0 then half 1, ascending indices)
        const bool f0 = (sl[t] == Lq);
        const bool f1 = (sl[t + 256] == Lq);
        const unsigned b0 = __ballot_sync(0xffffffffu, f0);
        const unsigned b1 = __ballot_sync(0xffffffffu, f1);
        if (lid == 0) { wcount[wid] = __popc(b0); wcount[8 + wid] = __popc(b1); }
        __syncthreads();                        // covers va + wcount
        int base0 = 0, base1 = 0, h1base = 0, M = 0;
        #pragma unroll
        for (int w = 0; w < 8; w++) {
            const int c0 = wcount[w], c1 = wcount[8 + w];
            base0 += (w < wid) ? c0 : 0;
            base1 += (w < wid) ? c1 : 0;
            h1base += c0;
            M += c0 + c1;
        }
        base1 += h1base;
        if (f0) mlist[base0 + __popc(b0 & ((1u << lid) - 1u))] = t;
        if (f1) mlist[base1 + __popc(b1 & ((1u << lid) - 1u))] = t + 256;
        __syncthreads();

        // direct rank per matched item; lane 0 accumulates its warp's contribs
        float wcontrib = 0.0f;
        for (int m = wid; m < M; m += 8) {
            const float vm = va[mlist[m]];      // broadcast LDS
            float acc = 0.0f;
            #pragma unroll
            for (int i = 0; i < 16; i++) {
                acc += fast_tanh(vm - va[lid + 32 * i]);
            }
            #pragma unroll
            for (int o = 16; o; o >>= 1) acc += __shfl_xor_sync(0xffffffffu, acc, o);
            if (lid == 0) {
                const float rank = 0.5f * (float)NQ + 0.5f * acc;
                wcontrib += 1.0f / (1.0f + __expf(rank - KSEL));  // sigmoid(K - rank)
            }
        }
        if (lid == 0) ws[wid] = wcontrib;
        __syncthreads();
        if (t == 0) {
            float s = 0.0f;
            #pragma unroll
            for (int w = 0; w < 8; w++) s += ws[w];
            g_prec[q] = s;
            __threadfence();
            const unsigned tk = atomicAdd(&g_count, 1u);
            isLast = (tk == NQ - 1) ? 1 : 0;
        }
        __syncthreads();

        // last-finishing query block: deterministic final reduction -> loss
        if (isLast) {
            __threadfence();
            float v = g_prec[t] + g_prec[t + 256];
            #pragma unroll
            for (int o = 16; o; o >>= 1) v += __shfl_xor_sync(0xffffffffu, v, o);
            if (lid == 0) ws[wid] = v;
            __syncthreads();
            if (t == 0) {
                float s = 0.0f;
                #pragma unroll
                for (int w = 0; w < 8; w++) s += ws[w];
                out[0] = 1.0f - s / (KSEL * (float)NQ);
                g_count = 0;   // reset for next graph replay
                g_bar = 0;     // all blocks provably past the barrier
            }
        }
        __syncthreads();
    }
}

// ---------------------------------------------------------------------------
extern "C" void kernel_launch(void* const* d_in, const int* in_sizes, int n_in,
                              void* d_out, int out_size) {
    const float* F      = (const float*)d_in[0];
    const int*   labels = (const int*)d_in[1];
    float*       out    = (float*)d_out;

    static int nsm = 0;
    if (nsm == 0) {
        cudaDeviceGetAttribute(&nsm, cudaDevAttrMultiProcessorCount, 0);
        if (nsm <= 0) nsm = 148;
    }
    const int grid = 3 * nsm;   // __launch_bounds__(256,3) guarantees residency

    fused_kernel<<<grid, 256>>>(F, labels, out);
}

// round 17
// speedup vs baseline: 1.1560x; 1.1560x over previous
#include <cuda_runtime.h>
#include <math.h>

// Problem constants (fixed: features [512,384] f32, labels [512] i32)
#define NQ 512
#define DIM 384
#define KSPLIT 6
#define KCH 64               // K per gram job
#define TS 64                // gram tile size (M and N)
#define KC 16                // gram k-chunk
#define NJOBS (KSPLIT * (NQ / TS) * (NQ / TS))   // 384
#define NQBLOCKS (NQ / 2)    // 256 phase-2 blocks, 2 queries each
#define SCALE 50.0f          // 1/(2*t2): sigmoid(z) = 0.5 + 0.5*tanh(z/2)
#define KSEL 6.0f            // K = 5 + 1

// Scratch (no allocations allowed anywhere)
__device__ float g_part[KSPLIT * NQ * NQ];  // partial Gram matrices (6 MB, L2-resident)
__device__ float g_sqp[KSPLIT * NQ];        // partial diagonal (squared norms)
__device__ float g_prec[NQ];                // per-query precision sums
__device__ unsigned int g_bar = 0;          // grid barrier arrivals
__device__ unsigned int g_count = 0;        // per-block completion tickets (phase 2)

__device__ __forceinline__ float fast_tanh(float x) {
    float r;
    asm("tanh.approx.f32 %0, %1;" : "=f"(r) : "f"(x));
    return r;
}

// ---------------------------------------------------------------------------
// ONE persistent kernel (grid = 3 * #SM; launch_bounds guarantees residency).
//  Phase 1: gram jobs, plain-FFMA 4x4 microtile (known-good R12 body).
//  Grid barrier (all blocks resident).
//  Phase 2: block b < 256 handles queries 2b (warps 0-3) and 2b+1 (warps 4-7)
//           in ONE pass. Direct tanh-rank of label-matched items only.
// ---------------------------------------------------------------------------
__global__ __launch_bounds__(256, 3) void fused_kernel(const float* __restrict__ F,
                                                       const int* __restrict__ labels,
                                                       float* __restrict__ out) {
    __shared__ float As[KC][TS + 4];   // gram [k][m]
    __shared__ float Bs[KC][TS + 4];   // gram [k][n]
    __shared__ float sq[NQ];           // summed squared norms
    __shared__ float va0[NQ];          // distances for query q0
    __shared__ float va1[NQ];          // distances for query q1
    __shared__ int   sl[NQ];           // labels staged
    __shared__ int   ml0[NQ];          // matched list q0
    __shared__ int   ml1[NQ];          // matched list q1
    __shared__ int   wc[32];           // ballot counts: [0..15] q0, [16..31] q1
    __shared__ float ws[8];
    __shared__ int isLast;

    const int t   = threadIdx.x;
    const int wid = t >> 5;
    const int lid = t & 31;
    const unsigned GRID = gridDim.x;

    // ================= Phase 1: gram jobs (grid-stride; <=1 job/block) ======
    for (int job = blockIdx.x; job < NJOBS; job += GRID) {
        const int jz  = job >> 6;
        const int rem = job & 63;
        const int bm  = (rem >> 3) * TS;
        const int bn  = (rem & 7) * TS;
        const int kb  = jz * KCH;
        const int tr = t >> 4, tc = t & 15;
        const int lr = t >> 2, lc = (t & 3) * 4;

        float acc[4][4] = {};
        for (int k0 = kb; k0 < kb + KCH; k0 += KC) {
            float4 av = *reinterpret_cast<const float4*>(&F[(bm + lr) * DIM + k0 + lc]);
            As[lc + 0][lr] = av.x; As[lc + 1][lr] = av.y;
            As[lc + 2][lr] = av.z; As[lc + 3][lr] = av.w;
            float4 bv = *reinterpret_cast<const float4*>(&F[(bn + lr) * DIM + k0 + lc]);
            Bs[lc + 0][lr] = bv.x; Bs[lc + 1][lr] = bv.y;
            Bs[lc + 2][lr] = bv.z; Bs[lc + 3][lr] = bv.w;
            __syncthreads();
            #pragma unroll
            for (int kk = 0; kk < KC; kk++) {
                float4 a = *reinterpret_cast<const float4*>(&As[kk][4 * tr]);
                float4 b = *reinterpret_cast<const float4*>(&Bs[kk][4 * tc]);
                const float ar[4] = {a.x, a.y, a.z, a.w};
                const float br[4] = {b.x, b.y, b.z, b.w};
                #pragma unroll
                for (int i = 0; i < 4; i++)
                    #pragma unroll
                    for (int j = 0; j < 4; j++)
                        acc[i][j] = fmaf(ar[i], br[j], acc[i][j]);
            }
            __syncthreads();
        }
        float* dst = g_part + jz * (NQ * NQ);
        #pragma unroll
        for (int i = 0; i < 4; i++) {
            #pragma unroll
            for (int j = 0; j < 4; j++) {
                const int r = bm + 4 * tr + i;
                const int c = bn + 4 * tc + j;
                dst[r * NQ + c] = acc[i][j];
                if (r == c) g_sqp[jz * NQ + r] = acc[i][j];
            }
        }
    }

    // ================= Grid barrier (all blocks resident) ===================
    __syncthreads();
    if (t == 0) {
        __threadfence();
        atomicAdd(&g_bar, 1u);
        while (atomicAdd(&g_bar, 0u) < GRID) __nanosleep(64);
        __threadfence();
    }
    __syncthreads();

    // ================= Phase 2: 2 queries per block, ONE pass ===============
    const int b = blockIdx.x;
    if (b < NQBLOCKS) {
        const int q0 = 2 * b;
        const int q1 = 2 * b + 1;

        // norms + labels (coalesced)
        {
            float s0 = 0.0f, s1 = 0.0f;
            #pragma unroll
            for (int z = 0; z < KSPLIT; z++) {
                s0 += g_sqp[z * NQ + t];
                s1 += g_sqp[z * NQ + t + 256];
            }
            sq[t] = s0; sq[t + 256] = s1;
        }
        sl[t] = labels[t]; sl[t + 256] = labels[t + 256];

        // gram rows for both queries (coalesced, 24 independent LDG/thread)
        float a00 = 0.0f, a01 = 0.0f, a10 = 0.0f, a11 = 0.0f;
        {
            const int o0 = q0 * NQ;
            const int o1 = q1 * NQ;
            #pragma unroll
            for (int z = 0; z < KSPLIT; z++) {
                const int zz = z * NQ * NQ;
                a00 += g_part[zz + o0 + t];
                a01 += g_part[zz + o0 + t + 256];
                a10 += g_part[zz + o1 + t];
                a11 += g_part[zz + o1 + t + 256];
            }
        }
        __syncthreads();
        const float sqq0 = sq[q0], sqq1 = sq[q1];
        va0[t]       = SCALE * sqrtf(fmaxf(sqq0 + sq[t]       - 2.0f * a00, 0.0f));
        va0[t + 256] = SCALE * sqrtf(fmaxf(sqq0 + sq[t + 256] - 2.0f * a01, 0.0f));
        va1[t]       = SCALE * sqrtf(fmaxf(sqq1 + sq[t]       - 2.0f * a10, 0.0f));
        va1[t + 256] = SCALE * sqrtf(fmaxf(sqq1 + sq[t + 256] - 2.0f * a11, 0.0f));
        const int L0 = sl[q0], L1 = sl[q1];

        // deterministic matched lists for both queries (two halves each)
        const bool f0a = (sl[t] == L0), f0b = (sl[t + 256] == L0);
        const bool f1a = (sl[t] == L1), f1b = (sl[t + 256] == L1);
        const unsigned b0a = __ballot_sync(0xffffffffu, f0a);
        const unsigned b0b = __ballot_sync(0xffffffffu, f0b);
        const unsigned b1a = __ballot_sync(0xffffffffu, f1a);
        const unsigned b1b = __ballot_sync(0xffffffffu, f1b);
        if (lid == 0) {
            wc[wid]      = __popc(b0a);
            wc[8 + wid]  = __popc(b0b);
            wc[16 + wid] = __popc(b1a);
            wc[24 + wid] = __popc(b1b);
        }
        __syncthreads();                         // covers va* + wc
        int base0a = 0, base0b = 0, h0 = 0, M0 = 0;
        int base1a = 0, base1b = 0, h1 = 0, M1 = 0;
        #pragma unroll
        for (int w = 0; w < 8; w++) {
            const int c0a = wc[w], c0b = wc[8 + w];
            const int c1a = wc[16 + w], c1b = wc[24 + w];
            base0a += (w < wid) ? c0a : 0;
            base0b += (w < wid) ? c0b : 0;
            h0 += c0a; M0 += c0a + c0b;
            base1a += (w < wid) ? c1a : 0;
            base1b += (w < wid) ? c1b : 0;
            h1 += c1a; M1 += c1a + c1b;
        }
        base0b += h0;
        base1b += h1;
        if (f0a) ml0[base0a + __popc(b0a & ((1u << lid) - 1u))] = t;
        if (f0b) ml0[base0b + __popc(b0b & ((1u << lid) - 1u))] = t + 256;
        if (f1a) ml1[base1a + __popc(b1a & ((1u << lid) - 1u))] = t;
        if (f1b) ml1[base1b + __popc(b1b & ((1u << lid) - 1u))] = t + 256;
        __syncthreads();

        // warps 0-3 -> q0 items; warps 4-7 -> q1 items (lane-strided ranks)
        const int myq = wid >> 2;                // 0 or 1
        const int ww  = wid & 3;                 // warp within the query group
        const float* vaq = myq ? va1 : va0;
        const int*   mlq = myq ? ml1 : ml0;
        const int    Mq  = myq ? M1 : M0;
        float wcontrib = 0.0f;
        for (int m = ww; m < Mq; m += 4) {
            const float vm = vaq[mlq[m]];        // broadcast LDS
            float acc = 0.0f;
            #pragma unroll
            for (int i = 0; i < 16; i++) {
                acc += fast_tanh(vm - vaq[lid + 32 * i]);
            }
            #pragma unroll
            for (int o = 16; o; o >>= 1) acc += __shfl_xor_sync(0xffffffffu, acc, o);
            if (lid == 0) {
                const float rank = 0.5f * (float)NQ + 0.5f * acc;
                wcontrib += 1.0f / (1.0f + __expf(rank - KSEL));  // sigmoid(K - rank)
            }
        }
        if (lid == 0) ws[wid] = wcontrib;
        __syncthreads();
        if (t == 0) {
            g_prec[q0] = ws[0] + ws[1] + ws[2] + ws[3];
            g_prec[q1] = ws[4] + ws[5] + ws[6] + ws[7];
            __threadfence();
            const unsigned tk = atomicAdd(&g_count, 1u);
            isLast = (tk == NQBLOCKS - 1) ? 1 : 0;
        }
        __syncthreads();

        // last-finishing block: deterministic final reduction -> loss
        if (isLast) {
            __threadfence();
            float v = g_prec[t] + g_prec[t + 256];
            #pragma unroll
            for (int o = 16; o; o >>= 1) v += __shfl_xor_sync(0xffffffffu, v, o);
            if (lid == 0) ws[wid] = v;
            __syncthreads();
            if (t == 0) {
                float s = 0.0f;
                #pragma unroll
                for (int w = 0; w < 8; w++) s += ws[w];
                out[0] = 1.0f - s / (KSEL * (float)NQ);
                g_count = 0;   // reset for next graph replay
                g_bar = 0;     // all blocks provably past the barrier
            }
        }
    }
}

// ---------------------------------------------------------------------------
extern "C" void kernel_launch(void* const* d_in, const int* in_sizes, int n_in,
                              void* d_out, int out_size) {
    const float* F      = (const float*)d_in[0];
    const int*   labels = (const int*)d_in[1];
    float*       out    = (float*)d_out;

    static int nsm = 0;
    if (nsm == 0) {
        cudaDeviceGetAttribute(&nsm, cudaDevAttrMultiProcessorCount, 0);
        if (nsm <= 0) nsm = 148;
    }
    const int grid = 3 * nsm;   // __launch_bounds__(256,3) guarantees residency

    fused_kernel<<<grid, 256>>>(F, labels, out);
}